// round 14
// baseline (speedup 1.0000x reference)
#include <cuda_runtime.h>
#include <math.h>
#include <stdint.h>

#define B_    4
#define T_    2048
#define C_    1024
#define H_    16
#define D_    64
#define WIN_  256

// Scratch (device globals; no runtime allocation allowed)
__device__ float g_q[B_*H_*T_*D_];
__device__ float g_k[B_*H_*T_*D_];
__device__ float g_v[B_*H_*T_*D_];
__device__ __align__(16) float g_att[B_*T_*C_];   // PERMUTED-K + tf32 bits
// Pre-rounded + PERMUTED-K operand copies
__device__ __align__(16) float g_xr[B_*T_*C_];
__device__ __align__(16) float g_wqkv[3*C_*C_];
__device__ __align__(16) float g_wproj[C_*C_];

__device__ __forceinline__ uint32_t f2tf32(float x) {
    uint32_t r;
    asm("cvt.rna.tf32.f32 %0, %1;" : "=r"(r) : "f"(x));
    return r;
}

__device__ __forceinline__ void mma_tf32_16x8x8(
    float* d, const uint32_t* a, const uint32_t* b)
{
    asm volatile(
        "mma.sync.aligned.m16n8k8.row.col.f32.tf32.tf32.f32 "
        "{%0,%1,%2,%3}, {%4,%5,%6,%7}, {%8,%9}, {%0,%1,%2,%3};"
        : "+f"(d[0]), "+f"(d[1]), "+f"(d[2]), "+f"(d[3])
        : "r"(a[0]), "r"(a[1]), "r"(a[2]), "r"(a[3]),
          "r"(b[0]), "r"(b[1]));
}

__device__ __forceinline__ uint32_t smem_u32(const void* p) {
    uint32_t a;
    asm("{ .reg .u64 t; cvta.to.shared.u64 t, %1; cvt.u32.u64 %0, t; }"
        : "=r"(a) : "l"(p));
    return a;
}

__device__ __forceinline__ void cp16(uint32_t s, const void* g) {
    asm volatile("cp.async.cg.shared.global [%0], [%1], 16;"
                 :: "r"(s), "l"(g));
}
#define CP_COMMIT() asm volatile("cp.async.commit_group;" ::: "memory")
#define CP_WAIT(n)  asm volatile("cp.async.wait_group %0;" :: "n"(n) : "memory")

// ---------------------------------------------------------------------------
// Prepass: round fp32 -> tf32 bits AND permute K within 32-chunks:
//   c -> (c&3)*8 + (c>>2)   (so a-frag k-values become 8 contiguous words)
// Input read as float4 at c4 = lo (mult of 4): outputs go to hi + j*8 + lo/4.
// ---------------------------------------------------------------------------
template<int SEL>
__global__ void round_perm(const float4* __restrict__ src, int n4)
{
    float* dst = (SEL == 0) ? g_xr : (SEL == 1) ? g_wqkv : g_wproj;
    for (int i = blockIdx.x * blockDim.x + threadIdx.x; i < n4;
         i += gridDim.x * blockDim.x) {
        float4 v = src[i];
        int base = i << 2;
        int u  = (base & 31) >> 2;    // 0..7
        int hi = base & ~31;          // row*K + chunk*32
        dst[hi +      u] = __uint_as_float(f2tf32(v.x));
        dst[hi +  8 + u] = __uint_as_float(f2tf32(v.y));
        dst[hi + 16 + u] = __uint_as_float(f2tf32(v.z));
        dst[hi + 24 + u] = __uint_as_float(f2tf32(v.w));
    }
}

// ---------------------------------------------------------------------------
// tf32 GEMM, NT, PERMUTED-K operands. 128 threads, CTA 128x128x32, warp
// tile 64x64. 3-stage cp.async, one barrier per chunk (issue after barrier).
// Fragment loads are LDS.128: thread q reads words [q*8+4kkp, +4) of a row =
// both k-halves of kk=2kkp and 2kkp+1. 32 LDS.128/chunk (was 128 LDS.32).
// Banks: row g*36 + q*8 (+4kkp): all 32 banks distinct per phase (36%32=4).
// MODE 1: A=g_xr, B=g_wqkv, scatter q/k/v (pre-rounded tf32, NATURAL layout
//         for attention). MODE 2: A=g_att (permuted by attn), B=g_wproj.
// ---------------------------------------------------------------------------
#define KPAD 36
#define BUFW (2 * 128 * KPAD)
#define GSMEM_BYTES (3 * BUFW * 4)   // 110592 B

template<int MODE>
__global__ __launch_bounds__(128, 2) void gemm_cp(
    const float* __restrict__ bias,
    float* __restrict__ Cout,
    int M, int N, int K)
{
    extern __shared__ uint32_t sm[];
    const uint32_t sbase = smem_u32(sm);

    const float* __restrict__ A  = (MODE == 1) ? g_xr   : (const float*)g_att;
    const float* __restrict__ Bw = (MODE == 1) ? g_wqkv : g_wproj;

    const int tid  = threadIdx.x;
    const int w    = tid >> 5;
    const int lane = tid & 31;
    const int g    = lane >> 2;
    const int q    = lane & 3;
    const int wm   = w & 1;
    const int wn   = w >> 1;
    const int m0   = blockIdx.y * 128;
    const int n0   = blockIdx.x * 128;

    float acc[4][8][4];
    #pragma unroll
    for (int i = 0; i < 4; i++)
        #pragma unroll
        for (int j = 0; j < 8; j++)
            #pragma unroll
            for (int r = 0; r < 4; r++) acc[i][j][r] = 0.f;

    const int nch = K / 32;

    auto issue = [&](int cc) {
        const int k0 = cc * 32;
        const uint32_t as = sbase + (cc % 3) * BUFW * 4;
        const uint32_t bs = as + 128 * KPAD * 4;
        #pragma unroll
        for (int it = 0; it < 8; it++) {
            int f   = tid + it * 128;
            int row = f >> 3;
            int k4  = (f & 7) << 2;
            const uint32_t so = (uint32_t)(row * KPAD + k4) * 4;
            cp16(as + so, &A [(long)(m0 + row) * K + k0 + k4]);
            cp16(bs + so, &Bw[(long)(n0 + row) * K + k0 + k4]);
        }
        CP_COMMIT();
    };

    issue(0);
    issue(1);

    for (int c = 0; c < nch; c++) {
        if (c + 1 < nch) { CP_WAIT(1); } else { CP_WAIT(0); }
        __syncthreads();
        if (c + 2 < nch) issue(c + 2);

        const uint32_t* As = sm + (c % 3) * BUFW;
        const uint32_t* Bs = As + 128 * KPAD;

        #pragma unroll
        for (int kkp = 0; kkp < 2; kkp++) {
            const int co = q * 8 + kkp * 4;
            uint4 alo[4], ahi[4], bfr[8];
            #pragma unroll
            for (int im = 0; im < 4; im++) {
                const int mr = wm * 64 + im * 16 + g;
                alo[im] = *(const uint4*)&As[ mr      * KPAD + co];
                ahi[im] = *(const uint4*)&As[(mr + 8) * KPAD + co];
            }
            #pragma unroll
            for (int in = 0; in < 8; in++) {
                const int nc = wn * 64 + in * 8 + g;
                bfr[in] = *(const uint4*)&Bs[nc * KPAD + co];
            }
            #pragma unroll
            for (int im = 0; im < 4; im++) {
                uint32_t a0[4] = { alo[im].x, ahi[im].x, alo[im].y, ahi[im].y };
                uint32_t a1[4] = { alo[im].z, ahi[im].z, alo[im].w, ahi[im].w };
                #pragma unroll
                for (int in = 0; in < 8; in++) {
                    uint32_t b0[2] = { bfr[in].x, bfr[in].y };
                    uint32_t b1[2] = { bfr[in].z, bfr[in].w };
                    mma_tf32_16x8x8(acc[im][in], a0, b0);
                    mma_tf32_16x8x8(acc[im][in], a1, b1);
                }
            }
        }
    }

    // Epilogue (output n-dim is NOT permuted)
    #pragma unroll
    for (int im = 0; im < 4; im++) {
        #pragma unroll
        for (int in = 0; in < 8; in++) {
            const int mbase = m0 + wm * 64 + im * 16 + g;
            const int nbase = n0 + wn * 64 + in * 8 + q * 2;
            #pragma unroll
            for (int r = 0; r < 4; r++) {
                const int m = mbase + (r >> 1) * 8;
                const int n = nbase + (r & 1);
                float v = acc[im][in][r] + bias[n];
                if (MODE == 1) {
                    int s = n >> 10;
                    int h = (n >> 6) & 15;
                    int d = n & 63;
                    int b = m >> 11;
                    int t = m & 2047;
                    float* dst = (s == 0) ? g_q : (s == 1 ? g_k : g_v);
                    dst[(((long)(b * H_ + h)) * T_ + t) * D_ + d] =
                        __uint_as_float(f2tf32(v));
                } else {
                    Cout[(long)m * N + n] = v;
                }
            }
        }
    }
}

// ---------------------------------------------------------------------------
// Tensor-core windowed attention (R13 structure: 3-stage cp.async, one
// barrier/chunk, exp2 softmax). Epilogue stores g_att ROUNDED + PERMUTED-K
// so the proj GEMM consumes it directly.
// ---------------------------------------------------------------------------
#define QT  128
#define CK2 32
#define AST (2 * CK2 * 68)
#define ASMEM_BYTES (3 * AST * 4)          // 52224 B

__global__ __launch_bounds__(256, 2) void attn_mma_kernel()
{
    extern __shared__ uint32_t dsm[];
    __shared__ uint32_t p_s[8][16][36];

    const uint32_t sbase = smem_u32(dsm);
    const int tid  = threadIdx.x;
    const int w    = tid >> 5;
    const int lane = tid & 31;
    const int g    = lane >> 2;
    const int q    = lane & 3;
    const int q0   = blockIdx.x * QT;
    const int h    = blockIdx.y;
    const int b    = blockIdx.z;

    const long bh   = (long)(b * H_ + h);
    const float* Qp = g_q + bh * T_ * D_;
    const float* Kp = g_k + bh * T_ * D_;
    const float* Vp = g_v + bh * T_ * D_;

    const int qw  = q0 + w * 16;
    const int qg0 = qw + g;
    const int qg1 = qw + g + 8;

    const float SC = 0.18033688011f;   // 0.125 * log2(e)
    uint32_t aq[8][4];
    #pragma unroll
    for (int kk = 0; kk < 8; kk++) {
        aq[kk][0] = f2tf32(Qp[(long)qg0 * D_ + kk * 8 + q    ] * SC);
        aq[kk][1] = f2tf32(Qp[(long)qg1 * D_ + kk * 8 + q    ] * SC);
        aq[kk][2] = f2tf32(Qp[(long)qg0 * D_ + kk * 8 + q + 4] * SC);
        aq[kk][3] = f2tf32(Qp[(long)qg1 * D_ + kk * 8 + q + 4] * SC);
    }

    int lo_blk = q0 - (WIN_ - 1);
    if (lo_blk < 0) lo_blk = 0;
    lo_blk &= ~(CK2 - 1);
    const int nchunks = ((q0 + QT - 1) - lo_blk) / CK2 + 1;

    auto issue = [&](int cc) {
        const int ks = lo_blk + cc * CK2;
        const uint32_t kb = sbase + (cc % 3) * AST * 4;
        #pragma unroll
        for (int it = 0; it < 4; it++) {
            int f   = tid + it * 256;
            int mat = f >> 9;
            int idx = f & 511;
            int row = idx >> 4;
            int c4  = (idx & 15) << 2;
            const float* src = (mat ? Vp : Kp) + (long)(ks + row) * D_ + c4;
            cp16(kb + (uint32_t)(mat * (CK2 * 68) + row * 68 + c4) * 4, src);
        }
        CP_COMMIT();
    };

    float o[8][4];
    #pragma unroll
    for (int dt = 0; dt < 8; dt++)
        #pragma unroll
        for (int r = 0; r < 4; r++) o[dt][r] = 0.f;
    float m0r = -1e30f, m1r = -1e30f, l0 = 0.f, l1 = 0.f;

    issue(0);
    issue(1);

    for (int c = 0; c < nchunks; c++) {
        if (c + 1 < nchunks) { CP_WAIT(1); } else { CP_WAIT(0); }
        __syncthreads();
        if (c + 2 < nchunks) issue(c + 2);

        const int ks = lo_blk + c * CK2;
        if (ks > qw + 15 || ks + CK2 - 1 < qw - (WIN_ - 1)) continue;

        const uint32_t* ks_ = dsm + (c % 3) * AST;
        const uint32_t* vs_ = ks_ + CK2 * 68;

        float s[4][4];
        #pragma unroll
        for (int nt = 0; nt < 4; nt++)
            #pragma unroll
            for (int r = 0; r < 4; r++) s[nt][r] = 0.f;
        #pragma unroll
        for (int kk = 0; kk < 8; kk++) {
            uint32_t bf[4][2];
            #pragma unroll
            for (int nt = 0; nt < 4; nt++) {
                bf[nt][0] = ks_[(nt * 8 + g) * 68 + kk * 8 + q];
                bf[nt][1] = ks_[(nt * 8 + g) * 68 + kk * 8 + q + 4];
            }
            #pragma unroll
            for (int nt = 0; nt < 4; nt++)
                mma_tf32_16x8x8(s[nt], aq[kk], bf[nt]);
        }

        #pragma unroll
        for (int nt = 0; nt < 4; nt++) {
            const int j0 = ks + nt * 8 + 2 * q;
            const int j1 = j0 + 1;
            s[nt][0] = ((unsigned)(qg0 - j0) < WIN_) ? s[nt][0] : -1e30f;
            s[nt][1] = ((unsigned)(qg0 - j1) < WIN_) ? s[nt][1] : -1e30f;
            s[nt][2] = ((unsigned)(qg1 - j0) < WIN_) ? s[nt][2] : -1e30f;
            s[nt][3] = ((unsigned)(qg1 - j1) < WIN_) ? s[nt][3] : -1e30f;
        }

        float cm0 = -1e30f, cm1 = -1e30f;
        #pragma unroll
        for (int nt = 0; nt < 4; nt++) {
            cm0 = fmaxf(cm0, fmaxf(s[nt][0], s[nt][1]));
            cm1 = fmaxf(cm1, fmaxf(s[nt][2], s[nt][3]));
        }
        cm0 = fmaxf(cm0, __shfl_xor_sync(0xffffffffu, cm0, 1));
        cm0 = fmaxf(cm0, __shfl_xor_sync(0xffffffffu, cm0, 2));
        cm1 = fmaxf(cm1, __shfl_xor_sync(0xffffffffu, cm1, 1));
        cm1 = fmaxf(cm1, __shfl_xor_sync(0xffffffffu, cm1, 2));

        const float m0n = fmaxf(m0r, cm0), m1n = fmaxf(m1r, cm1);
        const float c0  = exp2f(m0r - m0n), c1 = exp2f(m1r - m1n);

        float p[4][4];
        float ps0 = 0.f, ps1 = 0.f;
        #pragma unroll
        for (int nt = 0; nt < 4; nt++) {
            p[nt][0] = exp2f(s[nt][0] - m0n);
            p[nt][1] = exp2f(s[nt][1] - m0n);
            p[nt][2] = exp2f(s[nt][2] - m1n);
            p[nt][3] = exp2f(s[nt][3] - m1n);
            ps0 += p[nt][0] + p[nt][1];
            ps1 += p[nt][2] + p[nt][3];
        }
        ps0 += __shfl_xor_sync(0xffffffffu, ps0, 1);
        ps0 += __shfl_xor_sync(0xffffffffu, ps0, 2);
        ps1 += __shfl_xor_sync(0xffffffffu, ps1, 1);
        ps1 += __shfl_xor_sync(0xffffffffu, ps1, 2);

        l0 = l0 * c0 + ps0;  m0r = m0n;
        l1 = l1 * c1 + ps1;  m1r = m1n;
        #pragma unroll
        for (int dt = 0; dt < 8; dt++) {
            o[dt][0] *= c0;  o[dt][1] *= c0;
            o[dt][2] *= c1;  o[dt][3] *= c1;
        }

        #pragma unroll
        for (int nt = 0; nt < 4; nt++) {
            uint2 u0, u1;
            u0.x = f2tf32(p[nt][0]); u0.y = f2tf32(p[nt][1]);
            u1.x = f2tf32(p[nt][2]); u1.y = f2tf32(p[nt][3]);
            *(uint2*)&p_s[w][g    ][nt * 8 + 2 * q] = u0;
            *(uint2*)&p_s[w][g + 8][nt * 8 + 2 * q] = u1;
        }
        __syncwarp();

        #pragma unroll
        for (int kk = 0; kk < 4; kk++) {
            uint32_t ap[4];
            ap[0] = p_s[w][g    ][kk * 8 + q];
            ap[1] = p_s[w][g + 8][kk * 8 + q];
            ap[2] = p_s[w][g    ][kk * 8 + q + 4];
            ap[3] = p_s[w][g + 8][kk * 8 + q + 4];
            #pragma unroll
            for (int dt = 0; dt < 8; dt++) {
                uint32_t bv[2];
                bv[0] = vs_[(kk * 8 + q    ) * 68 + dt * 8 + g];
                bv[1] = vs_[(kk * 8 + q + 4) * 68 + dt * 8 + g];
                mma_tf32_16x8x8(o[dt], ap, bv);
            }
        }
        __syncwarp();
    }

    // Epilogue: store ROUNDED + PERMUTED-K (c -> (c&3)*8 + c>>2 per 32-chunk)
    const float i0 = 1.f / l0, i1 = 1.f / l1;
    #pragma unroll
    for (int dt = 0; dt < 8; dt++) {
        #pragma unroll
        for (int e = 0; e < 2; e++) {
            const int col = h * D_ + dt * 8 + 2 * q + e;
            const int cb  = col & ~31;
            const int cc_ = col & 31;
            const int p_  = cb + ((cc_ & 3) << 3) + (cc_ >> 2);
            g_att[((long)(b * T_ + qg0)) * C_ + p_] =
                __uint_as_float(f2tf32(o[dt][e] * i0));
            g_att[((long)(b * T_ + qg1)) * C_ + p_] =
                __uint_as_float(f2tf32(o[dt][2 + e] * i1));
        }
    }
}

// ---------------------------------------------------------------------------
// Launch. Inputs identified by element count (all distinct).
// ---------------------------------------------------------------------------
extern "C" void kernel_launch(void* const* d_in, const int* in_sizes, int n_in,
                              void* d_out, int out_size)
{
    const float* x      = 0;
    const float* qkv_w  = 0;
    const float* qkv_b  = 0;
    const float* proj_w = 0;
    const float* proj_b = 0;

    for (int i = 0; i < n_in; i++) {
        switch (in_sizes[i]) {
            case B_ * T_ * C_:  x      = (const float*)d_in[i]; break; // 8388608
            case T_ * T_:       /* attn_mask — unused */         break; // 4194304
            case 3 * C_ * C_:   qkv_w  = (const float*)d_in[i]; break; // 3145728
            case 3 * C_:        qkv_b  = (const float*)d_in[i]; break; // 3072
            case C_ * C_:       proj_w = (const float*)d_in[i]; break; // 1048576
            case C_:            proj_b = (const float*)d_in[i]; break; // 1024
        }
    }

    float* out = (float*)d_out;

    cudaFuncSetAttribute(gemm_cp<1>,
        cudaFuncAttributeMaxDynamicSharedMemorySize, GSMEM_BYTES);
    cudaFuncSetAttribute(gemm_cp<2>,
        cudaFuncAttributeMaxDynamicSharedMemorySize, GSMEM_BYTES);
    cudaFuncSetAttribute(attn_mma_kernel,
        cudaFuncAttributeMaxDynamicSharedMemorySize, ASMEM_BYTES);

    // Prepass: round + permute operands in gmem
    round_perm<0><<<2048, 256>>>((const float4*)x,      (B_*T_*C_) / 4);
    round_perm<1><<<1024, 256>>>((const float4*)qkv_w,  (3*C_*C_) / 4);
    round_perm<2><<<512,  256>>>((const float4*)proj_w, (C_*C_) / 4);

    // QKV: g_xr [8192,1024] x g_wqkv [3072,1024]^T -> scatter q/k/v
    {
        dim3 grid(3 * C_ / 128, (B_ * T_) / 128);
        gemm_cp<1><<<grid, 128, GSMEM_BYTES>>>(qkv_b, nullptr,
                                               B_ * T_, 3 * C_, C_);
    }
    // Attention (tensor-core, 3-stage cp.async)
    {
        dim3 grid(T_ / QT, H_, B_);
        attn_mma_kernel<<<grid, 256, ASMEM_BYTES>>>();
    }
    // Proj: g_att [8192,1024] x g_wproj [1024,1024]^T -> out
    {
        dim3 grid(C_ / 128, (B_ * T_) / 128);
        gemm_cp<2><<<grid, 128, GSMEM_BYTES>>>(proj_b, out,
                                               B_ * T_, C_, C_);
    }
}

// round 15
// speedup vs baseline: 1.0654x; 1.0654x over previous
#include <cuda_runtime.h>
#include <math.h>
#include <stdint.h>

#define B_    4
#define T_    2048
#define C_    1024
#define H_    16
#define D_    64
#define WIN_  256

// Scratch (device globals; no runtime allocation allowed)
__device__ float g_q[B_*H_*T_*D_];
__device__ float g_k[B_*H_*T_*D_];
__device__ float g_v[B_*H_*T_*D_];
__device__ __align__(16) float g_att[B_*T_*C_];
// Pre-rounded (tf32-in-fp32-bits) operand copies
__device__ __align__(16) float g_xr[B_*T_*C_];
__device__ __align__(16) float g_wqkv[3*C_*C_];
__device__ __align__(16) float g_wproj[C_*C_];

__device__ __forceinline__ uint32_t f2tf32(float x) {
    uint32_t r;
    asm("cvt.rna.tf32.f32 %0, %1;" : "=r"(r) : "f"(x));
    return r;
}

__device__ __forceinline__ void mma_tf32_16x8x8(
    float* d, const uint32_t* a, const uint32_t* b)
{
    asm volatile(
        "mma.sync.aligned.m16n8k8.row.col.f32.tf32.tf32.f32 "
        "{%0,%1,%2,%3}, {%4,%5,%6,%7}, {%8,%9}, {%0,%1,%2,%3};"
        : "+f"(d[0]), "+f"(d[1]), "+f"(d[2]), "+f"(d[3])
        : "r"(a[0]), "r"(a[1]), "r"(a[2]), "r"(a[3]),
          "r"(b[0]), "r"(b[1]));
}

__device__ __forceinline__ uint32_t smem_u32(const void* p) {
    uint32_t a;
    asm("{ .reg .u64 t; cvta.to.shared.u64 t, %1; cvt.u32.u64 %0, t; }"
        : "=r"(a) : "l"(p));
    return a;
}

__device__ __forceinline__ void cp16(uint32_t s, const void* g) {
    asm volatile("cp.async.cg.shared.global [%0], [%1], 16;"
                 :: "r"(s), "l"(g));
}
#define CP_COMMIT() asm volatile("cp.async.commit_group;" ::: "memory")
#define CP_WAIT(n)  asm volatile("cp.async.wait_group %0;" :: "n"(n) : "memory")

// ---------------------------------------------------------------------------
// Prepass: round fp32 -> tf32 bits in gmem.
// ---------------------------------------------------------------------------
template<int SEL>
__global__ void round_tf32(const float4* __restrict__ src, int n4)
{
    float4* dst = (SEL == 0) ? (float4*)g_xr
                : (SEL == 1) ? (float4*)g_wqkv : (float4*)g_wproj;
    for (int i = blockIdx.x * blockDim.x + threadIdx.x; i < n4;
         i += gridDim.x * blockDim.x) {
        float4 v = src[i];
        v.x = __uint_as_float(f2tf32(v.x));
        v.y = __uint_as_float(f2tf32(v.y));
        v.z = __uint_as_float(f2tf32(v.z));
        v.w = __uint_as_float(f2tf32(v.w));
        dst[i] = v;
    }
}

// ---------------------------------------------------------------------------
// tf32 GEMM, NT. PERSISTENT: 296 CTAs grid-stride over output tiles (no
// tail wave). 128 threads, CTA tile 128x128x32, warp tile 64x64. 3-stage
// cp.async, one barrier per chunk (issue after barrier); extra barrier at
// tile top guards cross-tile smem stage reuse (chunk-31 readers of stage 1
// vs next tile's issue(1) writer).
// MODE 1: A=g_xr, B=g_wqkv, scatter q/k/v PRE-ROUNDED to tf32 bits.
// MODE 2: A=g_att (tf32 bits), B=g_wproj, plain fp32 out.
// ---------------------------------------------------------------------------
#define KPAD 36
#define BUFW (2 * 128 * KPAD)
#define GSMEM_BYTES (3 * BUFW * 4)   // 110592 B

template<int MODE>
__global__ __launch_bounds__(128, 2) void gemm_cp(
    const float* __restrict__ bias,
    float* __restrict__ Cout,
    int M, int N, int K)
{
    extern __shared__ uint32_t sm[];
    const uint32_t sbase = smem_u32(sm);

    const float* __restrict__ A  = (MODE == 1) ? g_xr   : (const float*)g_att;
    const float* __restrict__ Bw = (MODE == 1) ? g_wqkv : g_wproj;

    const int tid  = threadIdx.x;
    const int w    = tid >> 5;
    const int lane = tid & 31;
    const int g    = lane >> 2;
    const int q    = lane & 3;
    const int wm   = w & 1;
    const int wn   = w >> 1;

    const int nt_n   = N / 128;
    const int ntiles = (M / 128) * nt_n;
    const int nch    = K / 32;

    for (int tile = blockIdx.x; tile < ntiles; tile += gridDim.x) {
        const int m0 = (tile / nt_n) * 128;
        const int n0 = (tile % nt_n) * 128;

        // guard smem stage reuse across tiles
        __syncthreads();

        float acc[4][8][4];
        #pragma unroll
        for (int i = 0; i < 4; i++)
            #pragma unroll
            for (int j = 0; j < 8; j++)
                #pragma unroll
                for (int r = 0; r < 4; r++) acc[i][j][r] = 0.f;

        auto issue = [&](int cc) {
            const int k0 = cc * 32;
            const uint32_t as = sbase + (cc % 3) * BUFW * 4;
            const uint32_t bs = as + 128 * KPAD * 4;
            #pragma unroll
            for (int it = 0; it < 8; it++) {
                int f   = tid + it * 128;
                int row = f >> 3;
                int k4  = (f & 7) << 2;
                const uint32_t so = (uint32_t)(row * KPAD + k4) * 4;
                cp16(as + so, &A [(long)(m0 + row) * K + k0 + k4]);
                cp16(bs + so, &Bw[(long)(n0 + row) * K + k0 + k4]);
            }
            CP_COMMIT();
        };

        issue(0);
        issue(1);

        for (int c = 0; c < nch; c++) {
            if (c + 1 < nch) { CP_WAIT(1); } else { CP_WAIT(0); }
            __syncthreads();
            if (c + 2 < nch) issue(c + 2);

            const uint32_t* As = sm + (c % 3) * BUFW;
            const uint32_t* Bs = As + 128 * KPAD;

            #pragma unroll
            for (int kk = 0; kk < 4; kk++) {
                const int kb = kk * 8;
                uint32_t af[4][4], bf[8][2];
                #pragma unroll
                for (int im = 0; im < 4; im++) {
                    const int mr = wm * 64 + im * 16 + g;
                    af[im][0] = As[ mr      * KPAD + kb + q];
                    af[im][1] = As[(mr + 8) * KPAD + kb + q];
                    af[im][2] = As[ mr      * KPAD + kb + q + 4];
                    af[im][3] = As[(mr + 8) * KPAD + kb + q + 4];
                }
                #pragma unroll
                for (int in = 0; in < 8; in++) {
                    const int nc = wn * 64 + in * 8 + g;
                    bf[in][0] = Bs[nc * KPAD + kb + q];
                    bf[in][1] = Bs[nc * KPAD + kb + q + 4];
                }
                #pragma unroll
                for (int im = 0; im < 4; im++)
                    #pragma unroll
                    for (int in = 0; in < 8; in++)
                        mma_tf32_16x8x8(acc[im][in], af[im], bf[in]);
            }
        }

        // Epilogue
        #pragma unroll
        for (int im = 0; im < 4; im++) {
            #pragma unroll
            for (int in = 0; in < 8; in++) {
                const int mbase = m0 + wm * 64 + im * 16 + g;
                const int nbase = n0 + wn * 64 + in * 8 + q * 2;
                #pragma unroll
                for (int r = 0; r < 4; r++) {
                    const int m = mbase + (r >> 1) * 8;
                    const int n = nbase + (r & 1);
                    float v = acc[im][in][r] + bias[n];
                    if (MODE == 1) {
                        int s = n >> 10;
                        int h = (n >> 6) & 15;
                        int d = n & 63;
                        int b = m >> 11;
                        int t = m & 2047;
                        float* dst = (s == 0) ? g_q : (s == 1 ? g_k : g_v);
                        dst[(((long)(b * H_ + h)) * T_ + t) * D_ + d] =
                            __uint_as_float(f2tf32(v));
                    } else {
                        Cout[(long)m * N + n] = v;
                    }
                }
            }
        }
    }
}

// ---------------------------------------------------------------------------
// Tensor-core windowed attention (R13: 3-stage cp.async, one barrier/chunk,
// exp2 softmax, K/V row-major [key][68], p_s pad 36). Epilogue stores g_att
// rounded to tf32 bits for the proj GEMM.
// ---------------------------------------------------------------------------
#define QT  128
#define CK2 32
#define AST (2 * CK2 * 68)
#define ASMEM_BYTES (3 * AST * 4)          // 52224 B

__global__ __launch_bounds__(256, 2) void attn_mma_kernel()
{
    extern __shared__ uint32_t dsm[];
    __shared__ uint32_t p_s[8][16][36];

    const uint32_t sbase = smem_u32(dsm);
    const int tid  = threadIdx.x;
    const int w    = tid >> 5;
    const int lane = tid & 31;
    const int g    = lane >> 2;
    const int q    = lane & 3;
    const int q0   = blockIdx.x * QT;
    const int h    = blockIdx.y;
    const int b    = blockIdx.z;

    const long bh   = (long)(b * H_ + h);
    const float* Qp = g_q + bh * T_ * D_;
    const float* Kp = g_k + bh * T_ * D_;
    const float* Vp = g_v + bh * T_ * D_;

    const int qw  = q0 + w * 16;
    const int qg0 = qw + g;
    const int qg1 = qw + g + 8;

    const float SC = 0.18033688011f;   // 0.125 * log2(e)
    uint32_t aq[8][4];
    #pragma unroll
    for (int kk = 0; kk < 8; kk++) {
        aq[kk][0] = f2tf32(Qp[(long)qg0 * D_ + kk * 8 + q    ] * SC);
        aq[kk][1] = f2tf32(Qp[(long)qg1 * D_ + kk * 8 + q    ] * SC);
        aq[kk][2] = f2tf32(Qp[(long)qg0 * D_ + kk * 8 + q + 4] * SC);
        aq[kk][3] = f2tf32(Qp[(long)qg1 * D_ + kk * 8 + q + 4] * SC);
    }

    int lo_blk = q0 - (WIN_ - 1);
    if (lo_blk < 0) lo_blk = 0;
    lo_blk &= ~(CK2 - 1);
    const int nchunks = ((q0 + QT - 1) - lo_blk) / CK2 + 1;

    auto issue = [&](int cc) {
        const int ks = lo_blk + cc * CK2;
        const uint32_t kb = sbase + (cc % 3) * AST * 4;
        #pragma unroll
        for (int it = 0; it < 4; it++) {
            int f   = tid + it * 256;
            int mat = f >> 9;
            int idx = f & 511;
            int row = idx >> 4;
            int c4  = (idx & 15) << 2;
            const float* src = (mat ? Vp : Kp) + (long)(ks + row) * D_ + c4;
            cp16(kb + (uint32_t)(mat * (CK2 * 68) + row * 68 + c4) * 4, src);
        }
        CP_COMMIT();
    };

    float o[8][4];
    #pragma unroll
    for (int dt = 0; dt < 8; dt++)
        #pragma unroll
        for (int r = 0; r < 4; r++) o[dt][r] = 0.f;
    float m0r = -1e30f, m1r = -1e30f, l0 = 0.f, l1 = 0.f;

    issue(0);
    issue(1);

    for (int c = 0; c < nchunks; c++) {
        if (c + 1 < nchunks) { CP_WAIT(1); } else { CP_WAIT(0); }
        __syncthreads();
        if (c + 2 < nchunks) issue(c + 2);

        const int ks = lo_blk + c * CK2;
        if (ks > qw + 15 || ks + CK2 - 1 < qw - (WIN_ - 1)) continue;

        const uint32_t* ks_ = dsm + (c % 3) * AST;
        const uint32_t* vs_ = ks_ + CK2 * 68;

        float s[4][4];
        #pragma unroll
        for (int nt = 0; nt < 4; nt++)
            #pragma unroll
            for (int r = 0; r < 4; r++) s[nt][r] = 0.f;
        #pragma unroll
        for (int kk = 0; kk < 8; kk++) {
            uint32_t bf[4][2];
            #pragma unroll
            for (int nt = 0; nt < 4; nt++) {
                bf[nt][0] = ks_[(nt * 8 + g) * 68 + kk * 8 + q];
                bf[nt][1] = ks_[(nt * 8 + g) * 68 + kk * 8 + q + 4];
            }
            #pragma unroll
            for (int nt = 0; nt < 4; nt++)
                mma_tf32_16x8x8(s[nt], aq[kk], bf[nt]);
        }

        #pragma unroll
        for (int nt = 0; nt < 4; nt++) {
            const int j0 = ks + nt * 8 + 2 * q;
            const int j1 = j0 + 1;
            s[nt][0] = ((unsigned)(qg0 - j0) < WIN_) ? s[nt][0] : -1e30f;
            s[nt][1] = ((unsigned)(qg0 - j1) < WIN_) ? s[nt][1] : -1e30f;
            s[nt][2] = ((unsigned)(qg1 - j0) < WIN_) ? s[nt][2] : -1e30f;
            s[nt][3] = ((unsigned)(qg1 - j1) < WIN_) ? s[nt][3] : -1e30f;
        }

        float cm0 = -1e30f, cm1 = -1e30f;
        #pragma unroll
        for (int nt = 0; nt < 4; nt++) {
            cm0 = fmaxf(cm0, fmaxf(s[nt][0], s[nt][1]));
            cm1 = fmaxf(cm1, fmaxf(s[nt][2], s[nt][3]));
        }
        cm0 = fmaxf(cm0, __shfl_xor_sync(0xffffffffu, cm0, 1));
        cm0 = fmaxf(cm0, __shfl_xor_sync(0xffffffffu, cm0, 2));
        cm1 = fmaxf(cm1, __shfl_xor_sync(0xffffffffu, cm1, 1));
        cm1 = fmaxf(cm1, __shfl_xor_sync(0xffffffffu, cm1, 2));

        const float m0n = fmaxf(m0r, cm0), m1n = fmaxf(m1r, cm1);
        const float c0  = exp2f(m0r - m0n), c1 = exp2f(m1r - m1n);

        float p[4][4];
        float ps0 = 0.f, ps1 = 0.f;
        #pragma unroll
        for (int nt = 0; nt < 4; nt++) {
            p[nt][0] = exp2f(s[nt][0] - m0n);
            p[nt][1] = exp2f(s[nt][1] - m0n);
            p[nt][2] = exp2f(s[nt][2] - m1n);
            p[nt][3] = exp2f(s[nt][3] - m1n);
            ps0 += p[nt][0] + p[nt][1];
            ps1 += p[nt][2] + p[nt][3];
        }
        ps0 += __shfl_xor_sync(0xffffffffu, ps0, 1);
        ps0 += __shfl_xor_sync(0xffffffffu, ps0, 2);
        ps1 += __shfl_xor_sync(0xffffffffu, ps1, 1);
        ps1 += __shfl_xor_sync(0xffffffffu, ps1, 2);

        l0 = l0 * c0 + ps0;  m0r = m0n;
        l1 = l1 * c1 + ps1;  m1r = m1n;
        #pragma unroll
        for (int dt = 0; dt < 8; dt++) {
            o[dt][0] *= c0;  o[dt][1] *= c0;
            o[dt][2] *= c1;  o[dt][3] *= c1;
        }

        #pragma unroll
        for (int nt = 0; nt < 4; nt++) {
            uint2 u0, u1;
            u0.x = f2tf32(p[nt][0]); u0.y = f2tf32(p[nt][1]);
            u1.x = f2tf32(p[nt][2]); u1.y = f2tf32(p[nt][3]);
            *(uint2*)&p_s[w][g    ][nt * 8 + 2 * q] = u0;
            *(uint2*)&p_s[w][g + 8][nt * 8 + 2 * q] = u1;
        }
        __syncwarp();

        #pragma unroll
        for (int kk = 0; kk < 4; kk++) {
            uint32_t ap[4];
            ap[0] = p_s[w][g    ][kk * 8 + q];
            ap[1] = p_s[w][g + 8][kk * 8 + q];
            ap[2] = p_s[w][g    ][kk * 8 + q + 4];
            ap[3] = p_s[w][g + 8][kk * 8 + q + 4];
            #pragma unroll
            for (int dt = 0; dt < 8; dt++) {
                uint32_t bv[2];
                bv[0] = vs_[(kk * 8 + q    ) * 68 + dt * 8 + g];
                bv[1] = vs_[(kk * 8 + q + 4) * 68 + dt * 8 + g];
                mma_tf32_16x8x8(o[dt], ap, bv);
            }
        }
        __syncwarp();
    }

    // Epilogue: store pre-rounded tf32 bits (proj GEMM consumes directly)
    const float i0 = 1.f / l0, i1 = 1.f / l1;
    #pragma unroll
    for (int dt = 0; dt < 8; dt++) {
        const int d = dt * 8 + 2 * q;
        float2 o0, o1;
        o0.x = __uint_as_float(f2tf32(o[dt][0] * i0));
        o0.y = __uint_as_float(f2tf32(o[dt][1] * i0));
        o1.x = __uint_as_float(f2tf32(o[dt][2] * i1));
        o1.y = __uint_as_float(f2tf32(o[dt][3] * i1));
        *(float2*)&g_att[((long)(b * T_ + qg0)) * C_ + h * D_ + d] = o0;
        *(float2*)&g_att[((long)(b * T_ + qg1)) * C_ + h * D_ + d] = o1;
    }
}

// ---------------------------------------------------------------------------
// Launch. Inputs identified by element count (all distinct).
// ---------------------------------------------------------------------------
#define PERSIST_CTAS 296    // 148 SMs x 2 CTAs

extern "C" void kernel_launch(void* const* d_in, const int* in_sizes, int n_in,
                              void* d_out, int out_size)
{
    const float* x      = 0;
    const float* qkv_w  = 0;
    const float* qkv_b  = 0;
    const float* proj_w = 0;
    const float* proj_b = 0;

    for (int i = 0; i < n_in; i++) {
        switch (in_sizes[i]) {
            case B_ * T_ * C_:  x      = (const float*)d_in[i]; break; // 8388608
            case T_ * T_:       /* attn_mask — unused */         break; // 4194304
            case 3 * C_ * C_:   qkv_w  = (const float*)d_in[i]; break; // 3145728
            case 3 * C_:        qkv_b  = (const float*)d_in[i]; break; // 3072
            case C_ * C_:       proj_w = (const float*)d_in[i]; break; // 1048576
            case C_:            proj_b = (const float*)d_in[i]; break; // 1024
        }
    }

    float* out = (float*)d_out;

    cudaFuncSetAttribute(gemm_cp<1>,
        cudaFuncAttributeMaxDynamicSharedMemorySize, GSMEM_BYTES);
    cudaFuncSetAttribute(gemm_cp<2>,
        cudaFuncAttributeMaxDynamicSharedMemorySize, GSMEM_BYTES);
    cudaFuncSetAttribute(attn_mma_kernel,
        cudaFuncAttributeMaxDynamicSharedMemorySize, ASMEM_BYTES);

    // Prepass: round operands to tf32 bits in gmem
    round_tf32<0><<<2048, 256>>>((const float4*)x,      (B_*T_*C_) / 4);
    round_tf32<1><<<1024, 256>>>((const float4*)qkv_w,  (3*C_*C_) / 4);
    round_tf32<2><<<512,  256>>>((const float4*)proj_w, (C_*C_) / 4);

    // QKV: g_xr [8192,1024] x g_wqkv [3072,1024]^T -> scatter q/k/v
    gemm_cp<1><<<PERSIST_CTAS, 128, GSMEM_BYTES>>>(qkv_b, nullptr,
                                                   B_ * T_, 3 * C_, C_);
    // Attention (tensor-core, 3-stage cp.async)
    {
        dim3 grid(T_ / QT, H_, B_);
        attn_mma_kernel<<<grid, 256, ASMEM_BYTES>>>();
    }
    // Proj: g_att [8192,1024] x g_wproj [1024,1024]^T -> out
    gemm_cp<2><<<PERSIST_CTAS, 128, GSMEM_BYTES>>>(proj_b, out,
                                                   B_ * T_, C_, C_);
}